// round 12
// baseline (speedup 1.0000x reference)
#include <cuda_runtime.h>
#include <cuda_bf16.h>
#include <stdint.h>

// Fixed shapes: z_e [32,64,64,64] f32, codebook [512,64] f32
#define KCODES   512
#define CDIM     64
#define HW       4096
#define NTHREADS 256
#define TILE_M   128
#define CBPAD    66            // fp32 codebook row pad (264B pitch: float2-aligned, bank-spread)

// ---- SMEM layout (offsets within 1024-aligned base) ----
#define A_OFF    0                                // bf16 A tile 128x64, SW128-swizzled, 16384 B
#define B_OFF    16384                            // bf16 B tile 512x64, SW128-swizzled, 65536 B
#define CB_OFF   (B_OFF + KCODES*CDIM*2)          // fp32 padded codebook, 135168 B
#define CN_OFF   (CB_OFF + KCODES*CBPAD*4)        // cnorm, 2048 B
#define EXD_OFF  (CN_OFF + KCODES*4)              // per-(row,parity) sum|z| partials, 1024 B
#define EXM_OFF  (EXD_OFF + TILE_M*2*4)           // candidate masks [row][lane%4][4], 8192 B
#define REGION_BYTES (EXM_OFF + TILE_M*4*4*4)     // 228352
#define SMEM_DYN (REGION_BYTES + 1024)            // + align slack = 229376 (<= 232448 max optin)

#define SWZ(o) ((o) ^ (((o) >> 3) & 0x70))        // SW128 swizzle (XOR bits[6:4] with [9:7])

// ---------------- PTX helpers (all base sm_80/75 features — no 'a'-suffix) ----------------
__device__ __forceinline__ uint32_t smem_to_u32(const void* p) {
    uint32_t a;
    asm("{ .reg .u64 t; cvta.to.shared.u64 t, %1; cvt.u32.u64 %0, t; }" : "=r"(a) : "l"(p));
    return a;
}
#define LDMATRIX_X4(d0, d1, d2, d3, addr) \
    asm volatile("ldmatrix.sync.aligned.m8n8.x4.shared.b16 {%0,%1,%2,%3}, [%4];" \
        : "=r"(d0), "=r"(d1), "=r"(d2), "=r"(d3) : "r"(addr))

__device__ __forceinline__ void mma16816(float* c, const uint32_t* a,
                                         uint32_t b0, uint32_t b1) {
    asm volatile(
        "mma.sync.aligned.m16n8k16.row.col.f32.bf16.bf16.f32 "
        "{%0,%1,%2,%3}, {%4,%5,%6,%7}, {%8,%9}, {%0,%1,%2,%3};"
        : "+f"(c[0]), "+f"(c[1]), "+f"(c[2]), "+f"(c[3])
        : "r"(a[0]), "r"(a[1]), "r"(a[2]), "r"(a[3]), "r"(b0), "r"(b1));
}

// Exact emulation of the reference's fp32 distance (DO NOT reorder — gives rel_err 0.0):
//   dot = ascending-c fp32 fma chain; S = RN(zn + cn); d = RN(S - 2*dot)
__device__ __forceinline__ float exact_d(const float* zr, const float* crow,
                                         float zn, float cn) {
    float dot = 0.f;
    const float2* cr2 = reinterpret_cast<const float2*>(crow);
    #pragma unroll
    for (int c = 0; c < CDIM / 2; c++) {
        float2 cc = cr2[c];
        dot = fmaf(zr[2 * c    ], cc.x, dot);
        dot = fmaf(zr[2 * c + 1], cc.y, dot);
    }
    float S = zn + cn;
    return fmaf(-2.f, dot, S);
}

extern __shared__ char smem_raw[];

__global__ __launch_bounds__(NTHREADS, 1)
void vq_mma_kernel(const float* __restrict__ z,
                   const float* __restrict__ cb,
                   float* __restrict__ zq,
                   float* __restrict__ idx_out,
                   int n_tiles)
{
    const uint32_t smem_u = smem_to_u32(smem_raw);
    const uint32_t base_u = (smem_u + 1023u) & ~1023u;   // 1024-align for SW128
    char* base = smem_raw + (base_u - smem_u);

    float*    cbf32 = reinterpret_cast<float*>(base + CB_OFF);
    float*    cnorm = reinterpret_cast<float*>(base + CN_OFF);
    float*    exd2  = reinterpret_cast<float*>(base + EXD_OFF);
    unsigned* exm   = reinterpret_cast<unsigned*>(base + EXM_OFF);

    const int tid  = threadIdx.x;
    const int wid  = tid >> 5;
    const int lane = tid & 31;
    const int row  = tid & (TILE_M - 1);     // A-load / owner row
    const int par  = tid >> 7;               // 0: even channels, 1: odd channels

    // ---- stage codebook: fp32 padded copy + bf16 SW128 B tile + cnorm (once) ----
    for (int i = tid; i < KCODES * CDIM; i += NTHREADS) {
        int k = i >> 6, c = i & 63;
        float v = cb[i];
        cbf32[k * CBPAD + c] = v;
        *reinterpret_cast<__nv_bfloat16*>(base + B_OFF + SWZ((uint32_t)(k * 128 + c * 2)))
            = __float2bfloat16(v);
    }
    for (int k = tid; k < KCODES; k += NTHREADS) {
        const float* r = cb + k * CDIM;      // ascending-c fma: identical to refine's cn use
        float s = 0.f;
        #pragma unroll
        for (int c = 0; c < CDIM; c++) s = fmaf(r[c], r[c], s);
        cnorm[k] = s;
    }
    __syncthreads();

    float zev[32];                           // owner's even channels, captured during A-load

    for (int t = blockIdx.x; t < n_tiles; t += gridDim.x) {
        const int n0  = t * TILE_M;
        const int b   = n0 >> 12;
        const int hw0 = n0 & (HW - 1);       // 128-tiles never cross a batch boundary
        const float* zb = z + (size_t)b * (CDIM * HW) + hw0;

        // ---- A tile load: thread (row, par) loads channels par, par+2, ... ----
        float sa = 0.f;
        #pragma unroll
        for (int s = 0; s < 32; s++) {
            int c = par + 2 * s;
            float v = zb[c * HW + row];      // coalesced: lanes = consecutive rows
            if (par == 0) zev[s] = v;        // owners keep even channels
            sa += fabsf(v);
            *reinterpret_cast<__nv_bfloat16*>(base + A_OFF + SWZ((uint32_t)(row * 128 + c * 2)))
                = __float2bfloat16(v);
        }
        exd2[row * 2 + par] = sa;
        __syncthreads();

        // ---- A fragments: 4 k-steps, rows 16*wid..16*wid+15 (ldmatrix.x4) ----
        uint32_t af[4][4];
        {
            int r_l  = lane & 15;            // lanes 0-7,16-23 -> rows 0-7; 8-15,24-31 -> 8-15
            int kofs = (lane >> 4) * 8;
            #pragma unroll
            for (int kk = 0; kk < 4; kk++) {
                uint32_t off = (uint32_t)((16 * wid + r_l) * 128 + (16 * kk + kofs) * 2);
                uint32_t addr = base_u + A_OFF + SWZ(off);
                LDMATRIX_X4(af[kk][0], af[kk][1], af[kk][2], af[kk][3], addr);
            }
        }

        // ---- scan: 64 chunks of 8 codes; lane-local running best + candidate bitmask ----
        const int grp = lane >> 2;           // C-fragment row group (0..7)
        const int tq  = lane & 3;            // C-fragment col pair (cols 2tq, 2tq+1)
        const int r0  = 16 * wid + grp;      // global tile row of c0/c1
        const int r1  = r0 + 8;              // global tile row of c2/c3
        const float dlt0 = (exd2[2 * r0] + exd2[2 * r0 + 1]) * 2.5e-5f + 6e-5f;
        const float dlt1 = (exd2[2 * r1] + exd2[2 * r1 + 1]) * 2.5e-5f + 6e-5f;

        float best0 = 3.4e38f, thr0 = 3.4e38f;
        float best1 = 3.4e38f, thr1 = 3.4e38f;
        unsigned mA[4] = {0, 0, 0, 0};       // row r0: 64 chunks x 2 bits
        unsigned mB[4] = {0, 0, 0, 0};       // row r1

        const int bn = lane & 7;             // ldmatrix B row within chunk
        const int bk = (lane >> 3) * 8;      // ldmatrix B k-offset (0,8,16,24)

        #pragma unroll 4
        for (int nc = 0; nc < 64; nc++) {
            // B fragments: ldmatrix.x4 covers k 0..31 (regs 0,1 = kstep0; 2,3 = kstep1)
            uint32_t b0, b1, b2, b3, b4, b5, b6, b7;
            {
                uint32_t off0 = (uint32_t)((nc * 8 + bn) * 128 + bk * 2);
                uint32_t off1 = (uint32_t)((nc * 8 + bn) * 128 + (bk + 32) * 2);
                LDMATRIX_X4(b0, b1, b2, b3, base_u + B_OFF + SWZ(off0));
                LDMATRIX_X4(b4, b5, b6, b7, base_u + B_OFF + SWZ(off1));
            }
            float cfr[4] = {0.f, 0.f, 0.f, 0.f};
            mma16816(cfr, af[0], b0, b1);
            mma16816(cfr, af[1], b2, b3);
            mma16816(cfr, af[2], b4, b5);
            mma16816(cfr, af[3], b6, b7);

            // scores for cols (8nc + 2tq, +1); rows r0 (c0,c1) and r1 (c2,c3)
            float2 cn2 = *reinterpret_cast<const float2*>(&cnorm[nc * 8 + 2 * tq]);
            float s00 = fmaf(-2.f, cfr[0], cn2.x);
            float s01 = fmaf(-2.f, cfr[1], cn2.y);
            float s10 = fmaf(-2.f, cfr[2], cn2.x);
            float s11 = fmaf(-2.f, cfr[3], cn2.y);

            const int w  = nc >> 4;
            const int bi = 2 * (nc & 15);
            mA[w] |= (s00 < thr0) ? (1u << bi)       : 0u;
            mA[w] |= (s01 < thr0) ? (1u << (bi + 1)) : 0u;
            mB[w] |= (s10 < thr1) ? (1u << bi)       : 0u;
            mB[w] |= (s11 < thr1) ? (1u << (bi + 1)) : 0u;
            best0 = fminf(best0, fminf(s00, s01));  thr0 = best0 + dlt0;
            best1 = fminf(best1, fminf(s10, s11));  thr1 = best1 + dlt1;
        }

        // publish masks: exm[(row*4 + tq)*4 + w]
        #pragma unroll
        for (int w = 0; w < 4; w++) {
            exm[(r0 * 4 + tq) * 4 + w] = mA[w];
            exm[(r1 * 4 + tq) * 4 + w] = mB[w];
        }
        __syncthreads();

        // ---- owners (tid<128): exact refine over candidate union, then epilogue ----
        if (par == 0) {
            float zr[CDIM];
            #pragma unroll
            for (int s = 0; s < 32; s++) {
                zr[2 * s]     = zev[s];
                zr[2 * s + 1] = zb[(2 * s + 1) * HW + row];   // L2-hot re-fetch
            }
            float zn = 0.f;
            #pragma unroll
            for (int c = 0; c < CDIM; c++) zn = fmaf(zr[c], zr[c], zn);  // ascending

            int bidx = 0;
            float dbest = 3.4e38f;
            #pragma unroll 1
            for (int w = 0; w < 4; w++) {                    // 128-code blocks
                unsigned m0 = exm[(row * 4 + 0) * 4 + w];
                unsigned m1 = exm[(row * 4 + 1) * 4 + w];
                unsigned m2 = exm[(row * 4 + 2) * 4 + w];
                unsigned m3 = exm[(row * 4 + 3) * 4 + w];
                unsigned any = m0 | m1 | m2 | m3;
                if (!any) continue;
                #pragma unroll 1
                for (int c16 = 0; c16 < 16; c16++) {
                    unsigned sh = 2 * c16;
                    if (!((any >> sh) & 3u)) continue;
                    int kbase = 128 * w + 8 * c16;
                    // ascending k within chunk: lanes tq=0..3 cover cols 2tq, 2tq+1
                    unsigned bb0 = (m0 >> sh) & 3u, bb1 = (m1 >> sh) & 3u;
                    unsigned bb2 = (m2 >> sh) & 3u, bb3 = (m3 >> sh) & 3u;
                    unsigned packed = bb0 | (bb1 << 2) | (bb2 << 4) | (bb3 << 6);
                    while (packed) {
                        int bit = __ffs(packed) - 1;         // ascending col within chunk
                        packed &= packed - 1;
                        int k = kbase + bit;
                        float d = exact_d(zr, cbf32 + k * CBPAD, zn, cnorm[k]);
                        if (d < dbest) { dbest = d; bidx = k; }   // strict <, ascending k
                    }
                }
            }

            // z_q: channel-major scatter, coalesced across 128 owners per channel
            float* op = zq + (size_t)b * (CDIM * HW) + hw0 + row;
            const float2* crow = reinterpret_cast<const float2*>(cbf32 + bidx * CBPAD);
            #pragma unroll
            for (int c = 0; c < CDIM / 2; c++) {
                float2 v = crow[c];
                op[(2 * c) * HW]     = v.x;
                op[(2 * c + 1) * HW] = v.y;
            }
            if (idx_out) idx_out[n0 + row] = (float)bidx;
        }
        __syncthreads();                     // protect A tile + exm before next tile
    }
}

extern "C" void kernel_launch(void* const* d_in, const int* in_sizes, int n_in,
                              void* d_out, int out_size)
{
    const float* z  = (const float*)d_in[0];   // [32,64,64,64] f32
    const float* cb = (const float*)d_in[1];   // [512,64] f32

    const int n_total  = in_sizes[0] / CDIM;   // 131072
    const int zq_elems = in_sizes[0];          // 8388608
    const int n_tiles  = n_total / TILE_M;     // 1024

    float* zq = (float*)d_out;
    float* idx_out = nullptr;
    if (out_size >= zq_elems + n_total)
        idx_out = (float*)d_out + zq_elems;

    cudaFuncSetAttribute(vq_mma_kernel, cudaFuncAttributeMaxDynamicSharedMemorySize, SMEM_DYN);

    int sms = 148;
    cudaDeviceGetAttribute(&sms, cudaDevAttrMultiProcessorCount, 0);

    vq_mma_kernel<<<sms, NTHREADS, SMEM_DYN>>>(z, cb, zq, idx_out, n_tiles);
}

// round 13
// speedup vs baseline: 1.0035x; 1.0035x over previous
#include <cuda_runtime.h>
#include <cuda_bf16.h>
#include <stdint.h>

// Fixed shapes: z_e [32,64,64,64] f32, codebook [512,64] f32
#define KCODES   512
#define CDIM     64
#define HW       4096
#define NTHREADS 256
#define TILE_M   128
#define CBPAD    66            // fp32 codebook row pad (264B pitch: float2-aligned, bank-spread)

// ---- SMEM layout (offsets within 1024-aligned base) ----
#define A_OFF    0                                // bf16 A tile 128x64, SW128-swizzled, 16384 B
#define B_OFF    16384                            // bf16 B tile 512x64, SW128-swizzled, 65536 B
#define CB_OFF   (B_OFF + KCODES*CDIM*2)          // fp32 padded codebook, 135168 B
#define CN_OFF   (CB_OFF + KCODES*CBPAD*4)        // cnorm, 2048 B
#define EXD_OFF  (CN_OFF + KCODES*4)              // per-(row,parity) sum|z| partials, 1024 B
#define EXM_OFF  (EXD_OFF + TILE_M*2*4)           // candidate masks [row][lane%4][4], 8192 B
#define REGION_BYTES (EXM_OFF + TILE_M*4*4*4)     // 228352
#define SMEM_DYN (REGION_BYTES + 1024)            // + align slack = 229376 (<= 232448 max optin)

#define SWZ(o) ((o) ^ (((o) >> 3) & 0x70))        // SW128 swizzle (XOR bits[6:4] with [9:7])

// ---------------- PTX helpers (all base sm_80/75 features — no 'a'-suffix) ----------------
__device__ __forceinline__ uint32_t smem_to_u32(const void* p) {
    uint32_t a;
    asm("{ .reg .u64 t; cvta.to.shared.u64 t, %1; cvt.u32.u64 %0, t; }" : "=r"(a) : "l"(p));
    return a;
}
#define LDMATRIX_X4(d0, d1, d2, d3, addr) \
    asm volatile("ldmatrix.sync.aligned.m8n8.x4.shared.b16 {%0,%1,%2,%3}, [%4];" \
        : "=r"(d0), "=r"(d1), "=r"(d2), "=r"(d3) : "r"(addr))

__device__ __forceinline__ void mma16816(float* c, const uint32_t* a,
                                         uint32_t b0, uint32_t b1) {
    asm volatile(
        "mma.sync.aligned.m16n8k16.row.col.f32.bf16.bf16.f32 "
        "{%0,%1,%2,%3}, {%4,%5,%6,%7}, {%8,%9}, {%0,%1,%2,%3};"
        : "+f"(c[0]), "+f"(c[1]), "+f"(c[2]), "+f"(c[3])
        : "r"(a[0]), "r"(a[1]), "r"(a[2]), "r"(a[3]), "r"(b0), "r"(b1));
}

// Exact emulation of the reference's fp32 distance (DO NOT reorder — gives rel_err 0.0):
//   dot = ascending-c fp32 fma chain; S = RN(zn + cn); d = RN(S - 2*dot)
__device__ __forceinline__ float exact_d(const float* zr, const float* crow,
                                         float zn, float cn) {
    float dot = 0.f;
    const float2* cr2 = reinterpret_cast<const float2*>(crow);
    #pragma unroll
    for (int c = 0; c < CDIM / 2; c++) {
        float2 cc = cr2[c];
        dot = fmaf(zr[2 * c    ], cc.x, dot);
        dot = fmaf(zr[2 * c + 1], cc.y, dot);
    }
    float S = zn + cn;
    return fmaf(-2.f, dot, S);
}

extern __shared__ char smem_raw[];

__global__ __launch_bounds__(NTHREADS, 1)
void vq_mma_kernel(const float* __restrict__ z,
                   const float* __restrict__ cb,
                   float* __restrict__ zq,
                   float* __restrict__ idx_out,
                   int n_tiles)
{
    const uint32_t smem_u = smem_to_u32(smem_raw);
    const uint32_t base_u = (smem_u + 1023u) & ~1023u;   // 1024-align for SW128
    char* base = smem_raw + (base_u - smem_u);

    float*    cbf32 = reinterpret_cast<float*>(base + CB_OFF);
    float*    cnorm = reinterpret_cast<float*>(base + CN_OFF);
    float*    exd2  = reinterpret_cast<float*>(base + EXD_OFF);
    unsigned* exm   = reinterpret_cast<unsigned*>(base + EXM_OFF);

    const int tid  = threadIdx.x;
    const int wid  = tid >> 5;
    const int lane = tid & 31;
    const int row  = tid & (TILE_M - 1);     // A-load / owner row
    const int par  = tid >> 7;               // 0: even channels, 1: odd channels

    // ---- stage codebook: fp32 padded copy + bf16 SW128 B tile + cnorm (once) ----
    for (int i = tid; i < KCODES * CDIM; i += NTHREADS) {
        int k = i >> 6, c = i & 63;
        float v = cb[i];
        cbf32[k * CBPAD + c] = v;
        *reinterpret_cast<__nv_bfloat16*>(base + B_OFF + SWZ((uint32_t)(k * 128 + c * 2)))
            = __float2bfloat16(v);
    }
    for (int k = tid; k < KCODES; k += NTHREADS) {
        const float* r = cb + k * CDIM;      // ascending-c fma: identical to refine's cn use
        float s = 0.f;
        #pragma unroll
        for (int c = 0; c < CDIM; c++) s = fmaf(r[c], r[c], s);
        cnorm[k] = s;
    }
    __syncthreads();

    float zev[32];                           // owner's even channels, captured during A-load

    for (int t = blockIdx.x; t < n_tiles; t += gridDim.x) {
        const int n0  = t * TILE_M;
        const int b   = n0 >> 12;
        const int hw0 = n0 & (HW - 1);       // 128-tiles never cross a batch boundary
        const float* zb = z + (size_t)b * (CDIM * HW) + hw0;

        // ---- A tile load: thread (row, par) loads channels par, par+2, ... ----
        float sa = 0.f;
        #pragma unroll
        for (int s = 0; s < 32; s++) {
            int c = par + 2 * s;
            float v = zb[c * HW + row];      // coalesced: lanes = consecutive rows
            if (par == 0) zev[s] = v;        // owners keep even channels
            sa += fabsf(v);
            *reinterpret_cast<__nv_bfloat16*>(base + A_OFF + SWZ((uint32_t)(row * 128 + c * 2)))
                = __float2bfloat16(v);
        }
        exd2[row * 2 + par] = sa;
        __syncthreads();

        // ---- A fragments: 4 k-steps, rows 16*wid..16*wid+15 (ldmatrix.x4) ----
        uint32_t af[4][4];
        {
            int r_l  = lane & 15;            // lanes 0-7,16-23 -> rows 0-7; 8-15,24-31 -> 8-15
            int kofs = (lane >> 4) * 8;
            #pragma unroll
            for (int kk = 0; kk < 4; kk++) {
                uint32_t off = (uint32_t)((16 * wid + r_l) * 128 + (16 * kk + kofs) * 2);
                uint32_t addr = base_u + A_OFF + SWZ(off);
                LDMATRIX_X4(af[kk][0], af[kk][1], af[kk][2], af[kk][3], addr);
            }
        }

        // ---- scan: 64 chunks of 8 codes; lane-local running best + candidate bitmask ----
        const int grp = lane >> 2;           // C-fragment row group (0..7)
        const int tq  = lane & 3;            // C-fragment col pair (cols 2tq, 2tq+1)
        const int r0  = 16 * wid + grp;      // global tile row of c0/c1
        const int r1  = r0 + 8;              // global tile row of c2/c3
        const float dlt0 = (exd2[2 * r0] + exd2[2 * r0 + 1]) * 2.5e-5f + 6e-5f;
        const float dlt1 = (exd2[2 * r1] + exd2[2 * r1 + 1]) * 2.5e-5f + 6e-5f;

        float best0 = 3.4e38f, thr0 = 3.4e38f;
        float best1 = 3.4e38f, thr1 = 3.4e38f;
        unsigned mA[4] = {0, 0, 0, 0};       // row r0: 64 chunks x 2 bits
        unsigned mB[4] = {0, 0, 0, 0};       // row r1

        const int bn = lane & 7;             // ldmatrix B row within chunk
        const int bk = (lane >> 3) * 8;      // ldmatrix B k-offset (0,8,16,24)

        #pragma unroll 4
        for (int nc = 0; nc < 64; nc++) {
            // B fragments: ldmatrix.x4 covers k 0..31 (regs 0,1 = kstep0; 2,3 = kstep1)
            uint32_t b0, b1, b2, b3, b4, b5, b6, b7;
            {
                uint32_t off0 = (uint32_t)((nc * 8 + bn) * 128 + bk * 2);
                uint32_t off1 = (uint32_t)((nc * 8 + bn) * 128 + (bk + 32) * 2);
                LDMATRIX_X4(b0, b1, b2, b3, base_u + B_OFF + SWZ(off0));
                LDMATRIX_X4(b4, b5, b6, b7, base_u + B_OFF + SWZ(off1));
            }
            float cfr[4] = {0.f, 0.f, 0.f, 0.f};
            mma16816(cfr, af[0], b0, b1);
            mma16816(cfr, af[1], b2, b3);
            mma16816(cfr, af[2], b4, b5);
            mma16816(cfr, af[3], b6, b7);

            // scores for cols (8nc + 2tq, +1); rows r0 (c0,c1) and r1 (c2,c3)
            float2 cn2 = *reinterpret_cast<const float2*>(&cnorm[nc * 8 + 2 * tq]);
            float s00 = fmaf(-2.f, cfr[0], cn2.x);
            float s01 = fmaf(-2.f, cfr[1], cn2.y);
            float s10 = fmaf(-2.f, cfr[2], cn2.x);
            float s11 = fmaf(-2.f, cfr[3], cn2.y);

            const int w  = nc >> 4;
            const int bi = 2 * (nc & 15);
            mA[w] |= (s00 < thr0) ? (1u << bi)       : 0u;
            mA[w] |= (s01 < thr0) ? (1u << (bi + 1)) : 0u;
            mB[w] |= (s10 < thr1) ? (1u << bi)       : 0u;
            mB[w] |= (s11 < thr1) ? (1u << (bi + 1)) : 0u;
            best0 = fminf(best0, fminf(s00, s01));  thr0 = best0 + dlt0;
            best1 = fminf(best1, fminf(s10, s11));  thr1 = best1 + dlt1;
        }

        // publish masks: exm[(row*4 + tq)*4 + w]
        #pragma unroll
        for (int w = 0; w < 4; w++) {
            exm[(r0 * 4 + tq) * 4 + w] = mA[w];
            exm[(r1 * 4 + tq) * 4 + w] = mB[w];
        }
        __syncthreads();

        // ---- owners (tid<128): exact refine over candidate union, then epilogue ----
        if (par == 0) {
            float zr[CDIM];
            #pragma unroll
            for (int s = 0; s < 32; s++) {
                zr[2 * s]     = zev[s];
                zr[2 * s + 1] = zb[(2 * s + 1) * HW + row];   // L2-hot re-fetch
            }
            float zn = 0.f;
            #pragma unroll
            for (int c = 0; c < CDIM; c++) zn = fmaf(zr[c], zr[c], zn);  // ascending

            int bidx = 0;
            float dbest = 3.4e38f;
            #pragma unroll 1
            for (int w = 0; w < 4; w++) {                    // 128-code blocks
                unsigned m0 = exm[(row * 4 + 0) * 4 + w];
                unsigned m1 = exm[(row * 4 + 1) * 4 + w];
                unsigned m2 = exm[(row * 4 + 2) * 4 + w];
                unsigned m3 = exm[(row * 4 + 3) * 4 + w];
                unsigned any = m0 | m1 | m2 | m3;
                if (!any) continue;
                #pragma unroll 1
                for (int c16 = 0; c16 < 16; c16++) {
                    unsigned sh = 2 * c16;
                    if (!((any >> sh) & 3u)) continue;
                    int kbase = 128 * w + 8 * c16;
                    // ascending k within chunk: lanes tq=0..3 cover cols 2tq, 2tq+1
                    unsigned bb0 = (m0 >> sh) & 3u, bb1 = (m1 >> sh) & 3u;
                    unsigned bb2 = (m2 >> sh) & 3u, bb3 = (m3 >> sh) & 3u;
                    unsigned packed = bb0 | (bb1 << 2) | (bb2 << 4) | (bb3 << 6);
                    while (packed) {
                        int bit = __ffs(packed) - 1;         // ascending col within chunk
                        packed &= packed - 1;
                        int k = kbase + bit;
                        float d = exact_d(zr, cbf32 + k * CBPAD, zn, cnorm[k]);
                        if (d < dbest) { dbest = d; bidx = k; }   // strict <, ascending k
                    }
                }
            }

            // z_q: channel-major scatter, coalesced across 128 owners per channel
            float* op = zq + (size_t)b * (CDIM * HW) + hw0 + row;
            const float2* crow = reinterpret_cast<const float2*>(cbf32 + bidx * CBPAD);
            #pragma unroll
            for (int c = 0; c < CDIM / 2; c++) {
                float2 v = crow[c];
                op[(2 * c) * HW]     = v.x;
                op[(2 * c + 1) * HW] = v.y;
            }
            if (idx_out) idx_out[n0 + row] = (float)bidx;
        }
        __syncthreads();                     // protect A tile + exm before next tile
    }
}

extern "C" void kernel_launch(void* const* d_in, const int* in_sizes, int n_in,
                              void* d_out, int out_size)
{
    const float* z  = (const float*)d_in[0];   // [32,64,64,64] f32
    const float* cb = (const float*)d_in[1];   // [512,64] f32

    const int n_total  = in_sizes[0] / CDIM;   // 131072
    const int zq_elems = in_sizes[0];          // 8388608
    const int n_tiles  = n_total / TILE_M;     // 1024

    float* zq = (float*)d_out;
    float* idx_out = nullptr;
    if (out_size >= zq_elems + n_total)
        idx_out = (float*)d_out + zq_elems;

    cudaFuncSetAttribute(vq_mma_kernel, cudaFuncAttributeMaxDynamicSharedMemorySize, SMEM_DYN);

    int sms = 148;
    cudaDeviceGetAttribute(&sms, cudaDevAttrMultiProcessorCount, 0);

    vq_mma_kernel<<<sms, NTHREADS, SMEM_DYN>>>(z, cb, zq, idx_out, n_tiles);
}